// round 5
// baseline (speedup 1.0000x reference)
#include <cuda_runtime.h>
#include <math.h>

#define NN 8192
#define NEI 8
#define NE (NN*NEI)
#define EPSV 1e-5f

// ---------------- scratch (static device memory; no runtime alloc) -------------
__device__ float4 g_posq[NN];   // (x, y, z, |p|^2) all fp32
__device__ int    g_nbr[NE];
__device__ float  g_sh2[NE*5];
__device__ int    g_cnt[NN];
__device__ int    g_rowptr[NN+1];
__device__ int    g_cursor[NN];
__device__ int    g_csr[NE];
__device__ float  g_x0[NN*32];
__device__ float  g_x1[NN*48];
__device__ float  g_x2[NN*40];
__device__ float  g_y0[NN*32];
__device__ float  g_y1[NN*48];
__device__ float  g_y2[NN*40];
__device__ float  g_K[405];
__device__ float  g_scale0[32], g_shift0[32], g_scale1[16], g_scale2[8];

// K tensor layout offsets ([o][i][j] row-major per path)
// paths: (0,0,0)@0 sz1 | (0,2,2)@1 sz25 | (1,0,1)@26 sz9 | (1,2,1)@35 sz45 |
// (1,2,2)@80 sz75 | (2,0,2)@155 sz25 | (2,2,0)@180 sz25 | (2,2,1)@205 sz75 | (2,2,2)@280 sz125

// ---------------- K tensor init (mirrors _cg/_Q/_K in double) ------------------
__device__ double dfact(int n){ double r=1.0; for(int i=2;i<=n;i++) r*=(double)i; return r; }

__device__ double cg_coef(int j1,int m1,int j2,int m2,int j3,int m3){
  if(m1+m2!=m3 || j3<abs(j1-j2) || j3>j1+j2) return 0.0;
  double pre = sqrt((2.0*j3+1.0)*dfact(j3+j1-j2)*dfact(j3-j1+j2)*dfact(j1+j2-j3)/dfact(j1+j2+j3+1));
  pre *= sqrt(dfact(j3+m3)*dfact(j3-m3)*dfact(j1-m1)*dfact(j1+m1)*dfact(j2-m2)*dfact(j2+m2));
  double s=0.0;
  for(int k=0;k<=j1+j2-j3;k++){
    int d0=k, d1=j1+j2-j3-k, d2=j1-m1-k, d3=j2+m2-k, d4=j3-j2+m1+k, d5=j3-j1-m2+k;
    if(d0<0||d1<0||d2<0||d3<0||d4<0||d5<0) continue;
    double den = dfact(d0)*dfact(d1)*dfact(d2)*dfact(d3)*dfact(d4)*dfact(d5);
    s += ((k&1)? -1.0:1.0)/den;
  }
  return pre*s;
}

__device__ void q_entry(int l,int r,int c,double* re,double* im){
  int a=r-l, b=c-l; *re=0.0; *im=0.0;
  if(a==0 && b==0){ *re=1.0; return; }
  if(abs(a)!=abs(b) || a==0 || b==0) return;
  int m=abs(a); double s=0.7071067811865476; double sgn=(m&1)? -1.0:1.0;
  if(a==m && b==m)       *re = sgn*s;
  else if(a==m && b==-m) *re = s;
  else if(a==-m && b==m) *im = -sgn*s;
  else                   *im = s;
}

__global__ void k_initK(){
  const int L1[9]={0,0,1,1,1,2,2,2,2};
  const int L2[9]={0,2,0,2,2,0,2,2,2};
  const int L3[9]={0,2,1,1,2,2,0,1,2};
  const int OFF[9]={0,1,26,35,80,155,180,205,280};
  int p=blockIdx.x, t=threadIdx.x;
  int l1=L1[p], l2=L2[p], l3=L3[p];
  int d1=2*l1+1, d2=2*l2+1, d3=2*l3+1;
  int tot=d1*d2*d3;
  __shared__ float s_re[125], s_im[125];
  __shared__ int s_useim;
  double re=0.0, im=0.0;
  if(t<tot){
    int c=t/(d1*d2); int rem=t-(c*d1*d2); int a=rem/d2; int b=rem-a*d2;
    for(int C=0;C<d3;C++){
      double q3r,q3i; q_entry(l3,c,C,&q3r,&q3i); q3i=-q3i;  // conj
      if(q3r==0.0 && q3i==0.0) continue;
      for(int A=0;A<d1;A++){
        double q1r,q1i; q_entry(l1,a,A,&q1r,&q1i);
        if(q1r==0.0 && q1i==0.0) continue;
        for(int B=0;B<d2;B++){
          double q2r,q2i; q_entry(l2,b,B,&q2r,&q2i);
          if(q2r==0.0 && q2i==0.0) continue;
          double cgv = cg_coef(l1,A-l1,l2,B-l2,l3,C-l3);
          if(cgv==0.0) continue;
          double xr=q3r*q1r-q3i*q1i, xi=q3r*q1i+q3i*q1r;
          double yr=xr*q2r-xi*q2i,  yi=xr*q2i+xi*q2r;
          re += yr*cgv; im += yi*cgv;
        }
      }
    }
    s_re[t]=(float)re; s_im[t]=(float)im;
  }
  __syncthreads();
  if(t==0){
    float mr=0.f, mi=0.f;
    for(int k=0;k<tot;k++){ mr=fmaxf(mr,fabsf(s_re[k])); mi=fmaxf(mi,fabsf(s_im[k])); }
    s_useim = (mi>mr)?1:0;
  }
  __syncthreads();
  if(t<tot) g_K[OFF[p]+t] = s_useim ? s_im[t] : s_re[t];
}

// ---------------- prep -----------------------------------------------------
__global__ void k_prep(const float* __restrict__ pos){
  int n=blockIdx.x*blockDim.x+threadIdx.x;
  if(n>=NN) return;
  float x=pos[n*3+0], y=pos[n*3+1], z=pos[n*3+2];
  // sq: elementwise square then ascending reduce (XLA: mul, add, add)
  float sq = __fadd_rn(__fadd_rn(__fmul_rn(x,x),__fmul_rn(y,y)),__fmul_rn(z,z));
  float4 q; q.x=x; q.y=y; q.z=z; q.w=sq;
  g_posq[n]=q;
  g_cnt[n]=0;
}

__global__ void k_initx(const float* __restrict__ W_emb){
  int t=blockIdx.x*blockDim.x+threadIdx.x;
  if(t < NN*32)       g_x0[t] = W_emb[t & 31];
  else if(t < NN*80)  g_x1[t-NN*32] = 0.f;
  else if(t < NN*120) g_x2[t-NN*80] = 0.f;
}

// ---------------- KNN: warp per query, smem tiles, top-9 with tie-break -----
// GEMM-emulating dot: FMA chain ascending in k (cuBLAS SGEMM / XLA K-loop order).
__device__ __forceinline__ void topk_insert(float (&bv)[9], int (&bi)[9], float v, int j){
  if(v < bv[8] || (v==bv[8] && j<bi[8])){
    float cv=v; int ci=j;
    #pragma unroll
    for(int k=0;k<9;k++){
      bool sw = (cv<bv[k]) || (cv==bv[k] && ci<bi[k]);
      float tv=bv[k]; int ti=bi[k];
      if(sw){ bv[k]=cv; bi[k]=ci; cv=tv; ci=ti; }
    }
  }
}

__global__ void k_knn(){
  int warp = threadIdx.x>>5, lane = threadIdx.x&31;
  int i = blockIdx.x*8 + warp;
  float4 q = g_posq[i];
  float bv[9]; int bi[9];
  #pragma unroll
  for(int k=0;k<9;k++){ bv[k]=INFINITY; bi[k]=0x7fffffff; }
  __shared__ float4 tile[256];
  for(int jt=0; jt<NN; jt+=256){
    __syncthreads();
    tile[threadIdx.x] = g_posq[jt+threadIdx.x];
    __syncthreads();
    #pragma unroll
    for(int k=0;k<8;k++){
      int jj = lane + k*32;
      float4 p = tile[jj];
      // dot = fmaf(z*z', fmaf(y*y', rn(x*x')))  (ascending-k FMA chain)
      float dot = __fmaf_rn(q.z, p.z, __fmaf_rn(q.y, p.y, __fmul_rn(q.x, p.x)));
      // d2 = (sq_i + sq_j) - 2*dot, no contraction
      float d2  = __fsub_rn(__fadd_rn(q.w, p.w), __fmul_rn(2.f, dot));
      topk_insert(bv, bi, d2, jt+jj);
    }
  }
  // warp tree-merge of sorted 9-lists down to lane 0
  #pragma unroll
  for(int off=16; off>=1; off>>=1){
    float ov[9]; int oi[9];
    #pragma unroll
    for(int k=0;k<9;k++){
      ov[k]=__shfl_down_sync(0xffffffffu, bv[k], off);
      oi[k]=__shfl_down_sync(0xffffffffu, bi[k], off);
    }
    #pragma unroll
    for(int k=0;k<9;k++){
      if(ov[k] < bv[8] || (ov[k]==bv[8] && oi[k]<bi[8])) topk_insert(bv,bi,ov[k],oi[k]);
      else break;
    }
  }
  if(lane==0){
    #pragma unroll
    for(int r=0;r<8;r++) g_nbr[i*NEI+r] = bi[1+r];   // drop slot 0 (self), like idx[:,1:]
  }
}

// ---------------- edge geometry (sh2) + in-degree histogram -----------------
__global__ void k_edgegeo(const float* __restrict__ pos){
  int e=blockIdx.x*blockDim.x+threadIdx.x;
  if(e>=NE) return;
  int s=e>>3; int d=g_nbr[e];
  float ex=pos[d*3+0]-pos[s*3+0];
  float ey=pos[d*3+1]-pos[s*3+1];
  float ez=pos[d*3+2]-pos[s*3+2];
  float nrm = sqrtf(ex*ex+ey*ey+ez*ez) + 1e-12f;
  float x=ex/nrm, y=ey/nrm, z=ez/nrm;
  const float s15 = 3.8729833462074170f;  // sqrt(15)
  const float s5  = 2.2360679774997896f;  // sqrt(5)
  g_sh2[e*5+0] = s15*x*y;
  g_sh2[e*5+1] = s15*y*z;
  g_sh2[e*5+2] = 0.5f*s5*(3.f*z*z-1.f);
  g_sh2[e*5+3] = s15*x*z;
  g_sh2[e*5+4] = 0.5f*s15*(x*x-y*y);
  atomicAdd(&g_cnt[d],1);
}

// ---------------- exclusive scan (1 block) ----------------------------------
__global__ void k_scan(){
  __shared__ int tsum[1024];
  int t=threadIdx.x;
  int base=t*8; int local[8]; int s=0;
  #pragma unroll
  for(int k=0;k<8;k++){ local[k]=s; s+=g_cnt[base+k]; }
  tsum[t]=s; __syncthreads();
  for(int off=1; off<1024; off<<=1){
    int v = (t>=off)? tsum[t-off] : 0;
    __syncthreads();
    tsum[t]+=v;
    __syncthreads();
  }
  int prev = (t==0)?0:tsum[t-1];
  #pragma unroll
  for(int k=0;k<8;k++){ int val=prev+local[k]; g_rowptr[base+k]=val; g_cursor[base+k]=val; }
  if(t==1023) g_rowptr[NN]=tsum[1023];
}

__global__ void k_scatter(){
  int e=blockIdx.x*blockDim.x+threadIdx.x;
  if(e>=NE) return;
  int d=g_nbr[e];
  int p=atomicAdd(&g_cursor[d],1);
  g_csr[p]=e;
}

// sort each CSR row ascending -> fully deterministic aggregation order
__global__ void k_sortrows(){
  int n=blockIdx.x*blockDim.x+threadIdx.x;
  if(n>=NN) return;
  int b=g_rowptr[n], e2=g_rowptr[n+1];
  for(int i=b+1;i<e2;i++){
    int v=g_csr[i]; int j=i-1;
    while(j>=b && g_csr[j]>v){ g_csr[j+1]=g_csr[j]; j--; }
    g_csr[j+1]=v;
  }
}

// ---------------- per-slot message value ------------------------------------
__device__ __forceinline__ float slot_val(int s, const float* xs, const float* sK, const float* sw){
  const float* x0=xs; const float* x1=xs+32; const float* x2=xs+80; const float* sh=xs+120;
  if(s<40){
    if(s<32) return x0[s]*sK[0]*sw[s];                       // p1 (0,0,0)
    int u=s-32; float t=0.f;                                  // p7 (2,2,0)
    #pragma unroll
    for(int i=0;i<5;i++){
      #pragma unroll
      for(int j=0;j<5;j++) t += x2[u*5+i]*sh[j]*sK[180+i*5+j];
    }
    return t*sw[120+u];
  } else if(s<160){
    int q=s-40; int u=q/3, m=q-3*u;
    if(u<16){                                                 // p3 (1,0,1)
      float t=0.f;
      #pragma unroll
      for(int i=0;i<3;i++) t += x1[u*3+i]*sK[26+m*3+i];
      return t*sw[64+u];
    }
    if(u<32){                                                 // p4 (1,2,1)
      int uu=u-16; float t=0.f;
      #pragma unroll
      for(int i=0;i<3;i++){
        #pragma unroll
        for(int j=0;j<5;j++) t += x1[uu*3+i]*sh[j]*sK[35+m*15+i*5+j];
      }
      return t*sw[80+uu];
    }
    int uu=u-32; float t=0.f;                                 // p8 (2,2,1)
    #pragma unroll
    for(int i=0;i<5;i++){
      #pragma unroll
      for(int j=0;j<5;j++) t += x2[uu*5+i]*sh[j]*sK[205+m*25+i*5+j];
    }
    return t*sw[128+uu];
  } else {
    int q=s-160; int u=q/5, o=q-5*u;
    if(u<32){                                                 // p2 (0,2,2)
      float t=0.f;
      #pragma unroll
      for(int j=0;j<5;j++) t += sK[1+o*5+j]*sh[j];
      return x0[u]*t*sw[32+u];
    }
    if(u<48){                                                 // p5 (1,2,2)
      int uu=u-32; float t=0.f;
      #pragma unroll
      for(int i=0;i<3;i++){
        #pragma unroll
        for(int j=0;j<5;j++) t += x1[uu*3+i]*sh[j]*sK[80+o*15+i*5+j];
      }
      return t*sw[96+uu];
    }
    if(u<56){                                                 // p6 (2,0,2)
      int uu=u-48; float t=0.f;
      #pragma unroll
      for(int i=0;i<5;i++) t += x2[uu*5+i]*sK[155+o*5+i];
      return t*sw[112+uu];
    }
    int uu=u-56; float t=0.f;                                 // p9 (2,2,2)
    #pragma unroll
    for(int i=0;i<5;i++){
      #pragma unroll
      for(int j=0;j<5;j++) t += x2[uu*5+i]*sh[j]*sK[280+o*25+i*5+j];
    }
    return t*sw[136+uu];
  }
}

// ---------------- aggregate + linear (block per dst node) -------------------
__global__ void k_aggregate(int l, const float* __restrict__ tp_w,
                            const float* __restrict__ W0g,
                            const float* __restrict__ W1g,
                            const float* __restrict__ W2g){
  int d=blockIdx.x; int t=threadIdx.x;
  __shared__ float sK[405];
  __shared__ float sw[144];
  __shared__ float xs[128];
  __shared__ float sa[480];
  for(int i=t;i<405;i+=128) sK[i]=g_K[i];
  for(int i=t;i<144;i+=128) sw[i]=tp_w[l*144+i];
  float acc0=0.f, acc1=0.f, acc2=0.f, acc3=0.f;
  int b=g_rowptr[d], deg=g_rowptr[d+1]-b;
  __syncthreads();
  for(int q=0;q<deg;q++){
    int e=g_csr[b+q]; int s=e>>3;
    if(t<32)       xs[t]=g_x0[s*32+t];
    else if(t<80)  xs[t]=g_x1[s*48+t-32];
    else if(t<120) xs[t]=g_x2[s*40+t-80];
    else if(t<125) xs[t]=g_sh2[e*5+t-120];
    __syncthreads();
    acc0 += slot_val(t,     xs, sK, sw);
    acc1 += slot_val(t+128, xs, sK, sw);
    acc2 += slot_val(t+256, xs, sK, sw);
    if(t<96) acc3 += slot_val(t+384, xs, sK, sw);
    __syncthreads();
  }
  sa[t]=acc0; sa[t+128]=acc1; sa[t+256]=acc2; if(t<96) sa[t+384]=acc3;
  __syncthreads();
  const float* W0=W0g+l*1280; const float* W1=W1g+l*640; const float* W2=W2g+l*512;
  const float inv40 = 0.15811388300841897f;  // 1/sqrt(40)
  if(t<32){
    float s=0.f;
    #pragma unroll
    for(int u=0;u<40;u++) s += sa[u]*__ldg(&W0[u*32+t]);
    g_y0[d*32+t] = s*inv40;
  } else if(t<80){
    int q2=t-32; int v=q2/3, m=q2-3*v; float s=0.f;
    #pragma unroll
    for(int u=0;u<40;u++) s += sa[40+u*3+m]*__ldg(&W1[u*16+v]);
    g_y1[d*48+v*3+m] = s*inv40;
  } else if(t<120){
    int q2=t-80; int v=q2/5, o=q2-5*v; float s=0.f;
    #pragma unroll
    for(int u=0;u<64;u++) s += sa[160+u*5+o]*__ldg(&W2[u*8+v]);
    g_y2[d*40+v*5+o] = s*0.125f;       // 1/sqrt(64)
  }
}

// ---------------- BN stats (deterministic, double accum) --------------------
__global__ void k_stats(int l, const float* __restrict__ bw0, const float* __restrict__ bb0,
                        const float* __restrict__ bw1, const float* __restrict__ bw2){
  int b=blockIdx.x, t=threadIdx.x;
  __shared__ double r1[256], r2[256];
  double s1=0.0, s2=0.0;
  if(b<32){
    int c=b;
    for(int n=t;n<NN;n+=256){ double v=g_y0[n*32+c]; s1+=v; s2+=v*v; }
  } else if(b<48){
    int c=b-32;
    for(int n=t;n<NN;n+=256){
      #pragma unroll
      for(int m=0;m<3;m++){ double v=g_y1[n*48+c*3+m]; s2+=v*v; }
    }
  } else {
    int c=b-48;
    for(int n=t;n<NN;n+=256){
      #pragma unroll
      for(int o=0;o<5;o++){ double v=g_y2[n*40+c*5+o]; s2+=v*v; }
    }
  }
  r1[t]=s1; r2[t]=s2; __syncthreads();
  for(int off=128; off>=1; off>>=1){
    if(t<off){ r1[t]+=r1[t+off]; r2[t]+=r2[t+off]; }
    __syncthreads();
  }
  if(t==0){
    if(b<32){
      int c=b;
      double mu=r1[0]/(double)NN;
      double var=r2[0]/(double)NN - mu*mu;
      float scale = bw0[l*32+c]/sqrtf((float)var + EPSV);
      g_scale0[c]=scale;
      g_shift0[c]=bb0[l*32+c]-(float)mu*scale;
    } else if(b<48){
      int c=b-32;
      float mean=(float)(r2[0]/(double)(NN*3));
      g_scale1[c]=bw1[l*16+c]/sqrtf(mean+EPSV);
    } else {
      int c=b-48;
      float mean=(float)(r2[0]/(double)(NN*5));
      g_scale2[c]=bw2[l*8+c]/sqrtf(mean+EPSV);
    }
  }
}

// ---------------- normalize + relu + residual -------------------------------
__global__ void k_update(){
  int t=blockIdx.x*blockDim.x+threadIdx.x;
  if(t>=NN*120) return;
  int n=t/120, r=t-n*120;
  if(r<32){
    int idx=n*32+r;
    float v=g_y0[idx]*g_scale0[r]+g_shift0[r];
    g_x0[idx]+=fmaxf(v,0.f);
  } else if(r<80){
    int q=r-32; int u=q/3; int idx=n*48+q;
    float v=g_y1[idx]*g_scale1[u];
    g_x1[idx]+=fmaxf(v,0.f);
  } else {
    int q=r-80; int u=q/5; int idx=n*40+q;
    float v=g_y2[idx]*g_scale2[u];
    g_x2[idx]+=fmaxf(v,0.f);
  }
}

// ---------------- head MLP ---------------------------------------------------
__global__ void k_head(const float* __restrict__ Wf1, const float* __restrict__ Wf2,
                       const float* __restrict__ bf2, const float* __restrict__ Wf3,
                       const float* __restrict__ bf3, float* __restrict__ out){
  __shared__ float sW1[1024], sW2[512], sb2[16], sW3[32], sb3[2];
  int t=threadIdx.x;
  for(int i=t;i<1024;i+=128) sW1[i]=Wf1[i];
  for(int i=t;i<512;i+=128)  sW2[i]=Wf2[i];
  if(t<16) sb2[t]=bf2[t];
  if(t<32) sW3[t]=Wf3[t];
  if(t<2)  sb3[t]=bf3[t];
  __syncthreads();
  int n=blockIdx.x*128+t;
  float xin[32];
  #pragma unroll
  for(int i=0;i<32;i++) xin[i]=g_x0[n*32+i];
  const float c1=0.1767766952966369f;  // 1/sqrt(32)
  float h1[32];
  #pragma unroll
  for(int j=0;j<32;j++){
    float s=0.f;
    #pragma unroll
    for(int i=0;i<32;i++) s += xin[i]*sW1[i*32+j];
    h1[j]=fmaxf(s*c1,0.f);
  }
  float h2[16];
  #pragma unroll
  for(int k=0;k<16;k++){
    float s=sb2[k];
    #pragma unroll
    for(int j=0;j<32;j++) s += h1[j]*sW2[j*16+k];
    h2[k]=fmaxf(s,0.f);
  }
  #pragma unroll
  for(int m=0;m<2;m++){
    float s=sb3[m];
    #pragma unroll
    for(int k=0;k<16;k++) s += h2[k]*sW3[k*2+m];
    out[n*2+m]=s;
  }
}

// ---------------- launch ------------------------------------------------------
extern "C" void kernel_launch(void* const* d_in, const int* in_sizes, int n_in,
                              void* d_out, int out_size){
  const float* pos    = (const float*)d_in[0];
  const float* W_emb  = (const float*)d_in[1];
  const float* tp_w   = (const float*)d_in[2];
  const float* lin_W0 = (const float*)d_in[3];
  const float* lin_W1 = (const float*)d_in[4];
  const float* lin_W2 = (const float*)d_in[5];
  const float* bn_w0  = (const float*)d_in[6];
  const float* bn_b0  = (const float*)d_in[7];
  const float* bn_w1  = (const float*)d_in[8];
  const float* bn_w2  = (const float*)d_in[9];
  const float* Wf1    = (const float*)d_in[10];
  const float* Wf2    = (const float*)d_in[11];
  const float* bf2    = (const float*)d_in[12];
  const float* Wf3    = (const float*)d_in[13];
  const float* bf3    = (const float*)d_in[14];
  float* out = (float*)d_out;

  k_initK<<<9,128>>>();
  k_prep<<<NN/256,256>>>(pos);
  k_initx<<<(NN*120+255)/256,256>>>(W_emb);
  k_knn<<<NN/8,256>>>();
  k_edgegeo<<<NE/256,256>>>(pos);
  k_scan<<<1,1024>>>();
  k_scatter<<<NE/256,256>>>();
  k_sortrows<<<NN/256,256>>>();
  for(int l=0;l<3;l++){
    k_aggregate<<<NN,128>>>(l, tp_w, lin_W0, lin_W1, lin_W2);
    k_stats<<<56,256>>>(l, bn_w0, bn_b0, bn_w1, bn_w2);
    k_update<<<(NN*120+255)/256,256>>>();
  }
  k_head<<<NN/128,128>>>(Wf1, Wf2, bf2, Wf3, bf3, out);
}

// round 7
// speedup vs baseline: 1.1812x; 1.1812x over previous
#include <cuda_runtime.h>
#include <math.h>

#define NN 8192
#define NEI 8
#define NE (NN*NEI)
#define EPSV 1e-5f

// ---------------- scratch (static device memory; no runtime alloc) -------------
__device__ float4 g_posq[NN];   // (x, y, z, |p|^2) all fp32
__device__ int    g_nbr[NE];
__device__ float  g_sh2[NE*5];
__device__ int    g_cnt[NN];
__device__ int    g_rowptr[NN+1];
__device__ int    g_cursor[NN];
__device__ int    g_csr[NE];
__device__ float  g_x0[NN*32];
__device__ float  g_x1[NN*48];
__device__ float  g_x2[NN*40];
__device__ float  g_y0[NN*32];
__device__ float  g_y1[NN*48];
__device__ float  g_y2[NN*40];
__device__ float  g_K[405];
__device__ float  g_scale0[32], g_shift0[32], g_scale1[16], g_scale2[8];

// K tensor layout offsets ([o][i][j] row-major per path)
// paths: (0,0,0)@0 sz1 | (0,2,2)@1 sz25 | (1,0,1)@26 sz9 | (1,2,1)@35 sz45 |
// (1,2,2)@80 sz75 | (2,0,2)@155 sz25 | (2,2,0)@180 sz25 | (2,2,1)@205 sz75 | (2,2,2)@280 sz125

// ---------------- K tensor init (mirrors _cg/_Q/_K in double) ------------------
__device__ double dfact(int n){ double r=1.0; for(int i=2;i<=n;i++) r*=(double)i; return r; }

__device__ double cg_coef(int j1,int m1,int j2,int m2,int j3,int m3){
  if(m1+m2!=m3 || j3<abs(j1-j2) || j3>j1+j2) return 0.0;
  double pre = sqrt((2.0*j3+1.0)*dfact(j3+j1-j2)*dfact(j3-j1+j2)*dfact(j1+j2-j3)/dfact(j1+j2+j3+1));
  pre *= sqrt(dfact(j3+m3)*dfact(j3-m3)*dfact(j1-m1)*dfact(j1+m1)*dfact(j2-m2)*dfact(j2+m2));
  double s=0.0;
  for(int k=0;k<=j1+j2-j3;k++){
    int d0=k, d1=j1+j2-j3-k, d2=j1-m1-k, d3=j2+m2-k, d4=j3-j2+m1+k, d5=j3-j1-m2+k;
    if(d0<0||d1<0||d2<0||d3<0||d4<0||d5<0) continue;
    double den = dfact(d0)*dfact(d1)*dfact(d2)*dfact(d3)*dfact(d4)*dfact(d5);
    s += ((k&1)? -1.0:1.0)/den;
  }
  return pre*s;
}

__device__ void q_entry(int l,int r,int c,double* re,double* im){
  int a=r-l, b=c-l; *re=0.0; *im=0.0;
  if(a==0 && b==0){ *re=1.0; return; }
  if(abs(a)!=abs(b) || a==0 || b==0) return;
  int m=abs(a); double s=0.7071067811865476; double sgn=(m&1)? -1.0:1.0;
  if(a==m && b==m)       *re = sgn*s;
  else if(a==m && b==-m) *re = s;
  else if(a==-m && b==m) *im = -sgn*s;
  else                   *im = s;
}

__global__ void k_initK(){
  const int L1[9]={0,0,1,1,1,2,2,2,2};
  const int L2[9]={0,2,0,2,2,0,2,2,2};
  const int L3[9]={0,2,1,1,2,2,0,1,2};
  const int OFF[9]={0,1,26,35,80,155,180,205,280};
  int p=blockIdx.x, t=threadIdx.x;
  int l1=L1[p], l2=L2[p], l3=L3[p];
  int d1=2*l1+1, d2=2*l2+1, d3=2*l3+1;
  int tot=d1*d2*d3;
  __shared__ float s_re[125], s_im[125];
  __shared__ int s_useim;
  double re=0.0, im=0.0;
  if(t<tot){
    int c=t/(d1*d2); int rem=t-(c*d1*d2); int a=rem/d2; int b=rem-a*d2;
    for(int C=0;C<d3;C++){
      double q3r,q3i; q_entry(l3,c,C,&q3r,&q3i); q3i=-q3i;  // conj
      if(q3r==0.0 && q3i==0.0) continue;
      for(int A=0;A<d1;A++){
        double q1r,q1i; q_entry(l1,a,A,&q1r,&q1i);
        if(q1r==0.0 && q1i==0.0) continue;
        for(int B=0;B<d2;B++){
          double q2r,q2i; q_entry(l2,b,B,&q2r,&q2i);
          if(q2r==0.0 && q2i==0.0) continue;
          double cgv = cg_coef(l1,A-l1,l2,B-l2,l3,C-l3);
          if(cgv==0.0) continue;
          double xr=q3r*q1r-q3i*q1i, xi=q3r*q1i+q3i*q1r;
          double yr=xr*q2r-xi*q2i,  yi=xr*q2i+xi*q2r;
          re += yr*cgv; im += yi*cgv;
        }
      }
    }
    s_re[t]=(float)re; s_im[t]=(float)im;
  }
  __syncthreads();
  if(t==0){
    float mr=0.f, mi=0.f;
    for(int k=0;k<tot;k++){ mr=fmaxf(mr,fabsf(s_re[k])); mi=fmaxf(mi,fabsf(s_im[k])); }
    s_useim = (mi>mr)?1:0;
  }
  __syncthreads();
  if(t<tot) g_K[OFF[p]+t] = s_useim ? s_im[t] : s_re[t];
}

// ---------------- prep -----------------------------------------------------
__global__ void k_prep(const float* __restrict__ pos){
  int n=blockIdx.x*blockDim.x+threadIdx.x;
  if(n>=NN) return;
  float x=pos[n*3+0], y=pos[n*3+1], z=pos[n*3+2];
  float sq = __fadd_rn(__fadd_rn(__fmul_rn(x,x),__fmul_rn(y,y)),__fmul_rn(z,z));
  float4 q; q.x=x; q.y=y; q.z=z; q.w=sq;
  g_posq[n]=q;
  g_cnt[n]=0;
}

__global__ void k_initx(const float* __restrict__ W_emb){
  int t=blockIdx.x*blockDim.x+threadIdx.x;
  if(t < NN*32)       g_x0[t] = W_emb[t & 31];
  else if(t < NN*80)  g_x1[t-NN*32] = 0.f;
  else if(t < NN*120) g_x2[t-NN*80] = 0.f;
}

// ---------------- KNN (d2 arithmetic is frozen: matches reference bits) -----
__device__ __forceinline__ void topk_insert(float (&bv)[9], int (&bi)[9], float v, int j){
  // caller has already verified v <= bv[8]; equal-with-higher-index falls out bottom
  float cv=v; int ci=j;
  #pragma unroll
  for(int k=0;k<9;k++){
    bool sw = (cv<bv[k]) || (cv==bv[k] && ci<bi[k]);
    float tv=bv[k]; int ti=bi[k];
    if(sw){ bv[k]=cv; bi[k]=ci; cv=tv; ci=ti; }
  }
}

__global__ void k_knn(){
  int warp = threadIdx.x>>5, lane = threadIdx.x&31;
  int i = blockIdx.x*8 + warp;
  float4 q = g_posq[i];
  float bv[9]; int bi[9];
  #pragma unroll
  for(int k=0;k<9;k++){ bv[k]=INFINITY; bi[k]=0x7fffffff; }
  __shared__ float4 tile[256];
  for(int jt=0; jt<NN; jt+=256){
    __syncthreads();
    tile[threadIdx.x] = g_posq[jt+threadIdx.x];
    __syncthreads();
    #pragma unroll
    for(int k=0;k<8;k++){
      int jj = lane + k*32;
      float4 p = tile[jj];
      // dot = fmaf(z*z', fmaf(y*y', rn(x*x')))  (ascending-k FMA chain)
      float dot = __fmaf_rn(q.z, p.z, __fmaf_rn(q.y, p.y, __fmul_rn(q.x, p.x)));
      float d2  = __fsub_rn(__fadd_rn(q.w, p.w), __fmul_rn(2.f, dot));
      if(d2 <= bv[8]) topk_insert(bv, bi, d2, jt+jj);
    }
  }
  // warp tree-merge of sorted 9-lists down to lane 0
  #pragma unroll
  for(int off=16; off>=1; off>>=1){
    float ov[9]; int oi[9];
    #pragma unroll
    for(int k=0;k<9;k++){
      ov[k]=__shfl_down_sync(0xffffffffu, bv[k], off);
      oi[k]=__shfl_down_sync(0xffffffffu, bi[k], off);
    }
    #pragma unroll
    for(int k=0;k<9;k++){
      if(ov[k] <= bv[8]) topk_insert(bv,bi,ov[k],oi[k]);
      else break;
    }
  }
  if(lane==0){
    #pragma unroll
    for(int r=0;r<8;r++) g_nbr[i*NEI+r] = bi[1+r];   // drop slot 0 (self), like idx[:,1:]
  }
}

// ---------------- edge geometry (sh2) + in-degree histogram -----------------
__global__ void k_edgegeo(const float* __restrict__ pos){
  int e=blockIdx.x*blockDim.x+threadIdx.x;
  if(e>=NE) return;
  int s=e>>3; int d=g_nbr[e];
  float ex=pos[d*3+0]-pos[s*3+0];
  float ey=pos[d*3+1]-pos[s*3+1];
  float ez=pos[d*3+2]-pos[s*3+2];
  float nrm = sqrtf(ex*ex+ey*ey+ez*ez) + 1e-12f;
  float x=ex/nrm, y=ey/nrm, z=ez/nrm;
  const float s15 = 3.8729833462074170f;  // sqrt(15)
  const float s5  = 2.2360679774997896f;  // sqrt(5)
  g_sh2[e*5+0] = s15*x*y;
  g_sh2[e*5+1] = s15*y*z;
  g_sh2[e*5+2] = 0.5f*s5*(3.f*z*z-1.f);
  g_sh2[e*5+3] = s15*x*z;
  g_sh2[e*5+4] = 0.5f*s15*(x*x-y*y);
  atomicAdd(&g_cnt[d],1);
}

// ---------------- exclusive scan (1 block) ----------------------------------
__global__ void k_scan(){
  __shared__ int tsum[1024];
  int t=threadIdx.x;
  int base=t*8; int local[8]; int s=0;
  #pragma unroll
  for(int k=0;k<8;k++){ local[k]=s; s+=g_cnt[base+k]; }
  tsum[t]=s; __syncthreads();
  for(int off=1; off<1024; off<<=1){
    int v = (t>=off)? tsum[t-off] : 0;
    __syncthreads();
    tsum[t]+=v;
    __syncthreads();
  }
  int prev = (t==0)?0:tsum[t-1];
  #pragma unroll
  for(int k=0;k<8;k++){ int val=prev+local[k]; g_rowptr[base+k]=val; g_cursor[base+k]=val; }
  if(t==1023) g_rowptr[NN]=tsum[1023];
}

__global__ void k_scatter(){
  int e=blockIdx.x*blockDim.x+threadIdx.x;
  if(e>=NE) return;
  int d=g_nbr[e];
  int p=atomicAdd(&g_cursor[d],1);
  g_csr[p]=e;
}

// sort each CSR row ascending -> fully deterministic aggregation order
__global__ void k_sortrows(){
  int n=blockIdx.x*blockDim.x+threadIdx.x;
  if(n>=NN) return;
  int b=g_rowptr[n], e2=g_rowptr[n+1];
  for(int i=b+1;i<e2;i++){
    int v=g_csr[i]; int j=i-1;
    while(j>=b && g_csr[j]>v){ g_csr[j+1]=g_csr[j]; j--; }
    g_csr[j+1]=v;
  }
}

// ---------------- factored S: S_oi = sum_j K[o][i][j]*sh[j] -----------------
// sS layout: p2S@0(5: o) | p4S@5(9: m*3+i) | p5S@14(15: o*3+i) | p7S@29(5: i)
//            | p8S@34(15: m*5+i) | p9S@49(25: o*5+i)   total 74
__device__ __forceinline__ float compute_S(int t, const float* sh, const float* sK){
  int off; 
  if(t<5)       off = 1   + t*5;                               // p2: o=t
  else if(t<14){ int x=t-5;  off = 35  + (x/3)*15 + (x%3)*5; } // p4
  else if(t<29){ int x=t-14; off = 80  + (x/3)*15 + (x%3)*5; } // p5
  else if(t<34) off = 180 + (t-29)*5;                           // p7: i
  else if(t<49){ int x=t-34; off = 205 + (x/5)*25 + (x%5)*5; } // p8
  else         { int x=t-49; off = 280 + (x/5)*25 + (x%5)*5; } // p9
  float r = sK[off]*sh[0];
  r = __fmaf_rn(sK[off+1], sh[1], r);
  r = __fmaf_rn(sK[off+2], sh[2], r);
  r = __fmaf_rn(sK[off+3], sh[3], r);
  r = __fmaf_rn(sK[off+4], sh[4], r);
  return r;
}

// ---------------- per-slot message value (factored) -------------------------
__device__ __forceinline__ float slot_val2(int s, const float* X, const float* S,
                                           const float* sK, const float* sw){
  const float* x0=X; const float* x1=X+32; const float* x2=X+80;
  if(s<40){
    if(s<32) return x0[s]*sK[0]*sw[s];                         // p1 (0,0,0)
    int u=s-32; float t=0.f;                                    // p7 (2,2,0)
    #pragma unroll
    for(int i=0;i<5;i++) t = __fmaf_rn(x2[u*5+i], S[29+i], t);
    return t*sw[120+u];
  } else if(s<160){
    int q=s-40; int u=q/3, m=q-3*u;
    if(u<16){                                                   // p3 (1,0,1)
      float t=0.f;
      #pragma unroll
      for(int i=0;i<3;i++) t = __fmaf_rn(x1[u*3+i], sK[26+m*3+i], t);
      return t*sw[64+u];
    }
    if(u<32){                                                   // p4 (1,2,1)
      int uu=u-16; float t=0.f;
      #pragma unroll
      for(int i=0;i<3;i++) t = __fmaf_rn(x1[uu*3+i], S[5+m*3+i], t);
      return t*sw[80+uu];
    }
    int uu=u-32; float t=0.f;                                   // p8 (2,2,1)
    #pragma unroll
    for(int i=0;i<5;i++) t = __fmaf_rn(x2[uu*5+i], S[34+m*5+i], t);
    return t*sw[128+uu];
  } else {
    int q=s-160; int u=q/5, o=q-5*u;
    if(u<32) return x0[u]*S[o]*sw[32+u];                        // p2 (0,2,2)
    if(u<48){                                                   // p5 (1,2,2)
      int uu=u-32; float t=0.f;
      #pragma unroll
      for(int i=0;i<3;i++) t = __fmaf_rn(x1[uu*3+i], S[14+o*3+i], t);
      return t*sw[96+uu];
    }
    if(u<56){                                                   // p6 (2,0,2)
      int uu=u-48; float t=0.f;
      #pragma unroll
      for(int i=0;i<5;i++) t = __fmaf_rn(x2[uu*5+i], sK[155+o*5+i], t);
      return t*sw[112+uu];
    }
    int uu=u-56; float t=0.f;                                   // p9 (2,2,2)
    #pragma unroll
    for(int i=0;i<5;i++) t = __fmaf_rn(x2[uu*5+i], S[49+o*5+i], t);
    return t*sw[136+uu];
  }
}

__device__ __forceinline__ float load_edge_val(int t, int e){
  int s=e>>3;
  if(t<32)  return g_x0[s*32+t];
  if(t<80)  return g_x1[s*48+(t-32)];
  if(t<120) return g_x2[s*40+(t-80)];
  if(t<125) return g_sh2[e*5+(t-120)];
  return 0.f;
}

// ---------------- aggregate + linear (block per dst node) -------------------
// double-buffered smem, register prefetch of next edge, factored S
__global__ void k_aggregate(int l, const float* __restrict__ tp_w,
                            const float* __restrict__ W0g,
                            const float* __restrict__ W1g,
                            const float* __restrict__ W2g){
  int d=blockIdx.x; int t=threadIdx.x;
  __shared__ float sK[405];
  __shared__ float sw[144];
  __shared__ float xs[2][128];
  __shared__ float sS[2][80];
  __shared__ float sa[480];
  for(int i=t;i<405;i+=128) sK[i]=g_K[i];
  for(int i=t;i<144;i+=128) sw[i]=tp_w[l*144+i];
  float acc0=0.f, acc1=0.f, acc2=0.f, acc3=0.f;
  int b=g_rowptr[d], deg=g_rowptr[d+1]-b;
  float v = 0.f;
  if(deg>0) v = load_edge_val(t, g_csr[b]);
  __syncthreads();   // sK/sw ready
  for(int q=0;q<deg;q++){
    int buf=q&1;
    if(t<125) xs[buf][t]=v;
    __syncthreads();                                    // xs[buf] ready
    if(q+1<deg) v = load_edge_val(t, g_csr[b+q+1]);     // prefetch (overlaps)
    if(t<74) sS[buf][t] = compute_S(t, &xs[buf][120], sK);
    __syncthreads();                                    // sS[buf] ready
    const float* X=xs[buf]; const float* S=sS[buf];
    acc0 += slot_val2(t,     X, S, sK, sw);
    acc1 += slot_val2(t+128, X, S, sK, sw);
    acc2 += slot_val2(t+256, X, S, sK, sw);
    if(t<96) acc3 += slot_val2(t+384, X, S, sK, sw);
  }
  __syncthreads();
  sa[t]=acc0; sa[t+128]=acc1; sa[t+256]=acc2; if(t<96) sa[t+384]=acc3;
  __syncthreads();
  const float* W0=W0g+l*1280; const float* W1=W1g+l*640; const float* W2=W2g+l*512;
  const float inv40 = 0.15811388300841897f;  // 1/sqrt(40)
  if(t<32){
    float s=0.f;
    #pragma unroll
    for(int u=0;u<40;u++) s += sa[u]*__ldg(&W0[u*32+t]);
    g_y0[d*32+t] = s*inv40;
  } else if(t<80){
    int q2=t-32; int v2=q2/3, m=q2-3*v2; float s=0.f;
    #pragma unroll
    for(int u=0;u<40;u++) s += sa[40+u*3+m]*__ldg(&W1[u*16+v2]);
    g_y1[d*48+v2*3+m] = s*inv40;
  } else if(t<120){
    int q2=t-80; int v2=q2/5, o=q2-5*v2; float s=0.f;
    #pragma unroll
    for(int u=0;u<64;u++) s += sa[160+u*5+o]*__ldg(&W2[u*8+v2]);
    g_y2[d*40+v2*5+o] = s*0.125f;       // 1/sqrt(64)
  }
}

// ---------------- BN stats (deterministic, double accum) --------------------
__global__ void k_stats(int l, const float* __restrict__ bw0, const float* __restrict__ bb0,
                        const float* __restrict__ bw1, const float* __restrict__ bw2){
  int b=blockIdx.x, t=threadIdx.x;
  __shared__ double r1[256], r2[256];
  double s1=0.0, s2=0.0;
  if(b<32){
    int c=b;
    for(int n=t;n<NN;n+=256){ double v=g_y0[n*32+c]; s1+=v; s2+=v*v; }
  } else if(b<48){
    int c=b-32;
    for(int n=t;n<NN;n+=256){
      #pragma unroll
      for(int m=0;m<3;m++){ double v=g_y1[n*48+c*3+m]; s2+=v*v; }
    }
  } else {
    int c=b-48;
    for(int n=t;n<NN;n+=256){
      #pragma unroll
      for(int o=0;o<5;o++){ double v=g_y2[n*40+c*5+o]; s2+=v*v; }
    }
  }
  r1[t]=s1; r2[t]=s2; __syncthreads();
  for(int off=128; off>=1; off>>=1){
    if(t<off){ r1[t]+=r1[t+off]; r2[t]+=r2[t+off]; }
    __syncthreads();
  }
  if(t==0){
    if(b<32){
      int c=b;
      double mu=r1[0]/(double)NN;
      double var=r2[0]/(double)NN - mu*mu;
      float scale = bw0[l*32+c]/sqrtf((float)var + EPSV);
      g_scale0[c]=scale;
      g_shift0[c]=bb0[l*32+c]-(float)mu*scale;
    } else if(b<48){
      int c=b-32;
      float mean=(float)(r2[0]/(double)(NN*3));
      g_scale1[c]=bw1[l*16+c]/sqrtf(mean+EPSV);
    } else {
      int c=b-48;
      float mean=(float)(r2[0]/(double)(NN*5));
      g_scale2[c]=bw2[l*8+c]/sqrtf(mean+EPSV);
    }
  }
}

// ---------------- normalize + relu + residual -------------------------------
__global__ void k_update(){
  int t=blockIdx.x*blockDim.x+threadIdx.x;
  if(t>=NN*120) return;
  int n=t/120, r=t-n*120;
  if(r<32){
    int idx=n*32+r;
    float v=g_y0[idx]*g_scale0[r]+g_shift0[r];
    g_x0[idx]+=fmaxf(v,0.f);
  } else if(r<80){
    int q=r-32; int u=q/3; int idx=n*48+q;
    float v=g_y1[idx]*g_scale1[u];
    g_x1[idx]+=fmaxf(v,0.f);
  } else {
    int q=r-80; int u=q/5; int idx=n*40+q;
    float v=g_y2[idx]*g_scale2[u];
    g_x2[idx]+=fmaxf(v,0.f);
  }
}

// ---------------- head MLP ---------------------------------------------------
__global__ void k_head(const float* __restrict__ Wf1, const float* __restrict__ Wf2,
                       const float* __restrict__ bf2, const float* __restrict__ Wf3,
                       const float* __restrict__ bf3, float* __restrict__ out){
  __shared__ float sW1[1024], sW2[512], sb2[16], sW3[32], sb3[2];
  int t=threadIdx.x;
  for(int i=t;i<1024;i+=128) sW1[i]=Wf1[i];
  for(int i=t;i<512;i+=128)  sW2[i]=Wf2[i];
  if(t<16) sb2[t]=bf2[t];
  if(t<32) sW3[t]=Wf3[t];
  if(t<2)  sb3[t]=bf3[t];
  __syncthreads();
  int n=blockIdx.x*128+t;
  float xin[32];
  #pragma unroll
  for(int i=0;i<32;i++) xin[i]=g_x0[n*32+i];
  const float c1=0.1767766952966369f;  // 1/sqrt(32)
  float h1[32];
  #pragma unroll
  for(int j=0;j<32;j++){
    float s=0.f;
    #pragma unroll
    for(int i=0;i<32;i++) s += xin[i]*sW1[i*32+j];
    h1[j]=fmaxf(s*c1,0.f);
  }
  float h2[16];
  #pragma unroll
  for(int k=0;k<16;k++){
    float s=sb2[k];
    #pragma unroll
    for(int j=0;j<32;j++) s += h1[j]*sW2[j*16+k];
    h2[k]=fmaxf(s,0.f);
  }
  #pragma unroll
  for(int m=0;m<2;m++){
    float s=sb3[m];
    #pragma unroll
    for(int k=0;k<16;k++) s += h2[k]*sW3[k*2+m];
    out[n*2+m]=s;
  }
}

// ---------------- launch ------------------------------------------------------
extern "C" void kernel_launch(void* const* d_in, const int* in_sizes, int n_in,
                              void* d_out, int out_size){
  const float* pos    = (const float*)d_in[0];
  const float* W_emb  = (const float*)d_in[1];
  const float* tp_w   = (const float*)d_in[2];
  const float* lin_W0 = (const float*)d_in[3];
  const float* lin_W1 = (const float*)d_in[4];
  const float* lin_W2 = (const float*)d_in[5];
  const float* bn_w0  = (const float*)d_in[6];
  const float* bn_b0  = (const float*)d_in[7];
  const float* bn_w1  = (const float*)d_in[8];
  const float* bn_w2  = (const float*)d_in[9];
  const float* Wf1    = (const float*)d_in[10];
  const float* Wf2    = (const float*)d_in[11];
  const float* bf2    = (const float*)d_in[12];
  const float* Wf3    = (const float*)d_in[13];
  const float* bf3    = (const float*)d_in[14];
  float* out = (float*)d_out;

  k_initK<<<9,128>>>();
  k_prep<<<NN/256,256>>>(pos);
  k_initx<<<(NN*120+255)/256,256>>>(W_emb);
  k_knn<<<NN/8,256>>>();
  k_edgegeo<<<NE/256,256>>>(pos);
  k_scan<<<1,1024>>>();
  k_scatter<<<NE/256,256>>>();
  k_sortrows<<<NN/256,256>>>();
  for(int l=0;l<3;l++){
    k_aggregate<<<NN,128>>>(l, tp_w, lin_W0, lin_W1, lin_W2);
    k_stats<<<56,256>>>(l, bn_w0, bn_b0, bn_w1, bn_w2);
    k_update<<<(NN*120+255)/256,256>>>();
  }
  k_head<<<NN/128,128>>>(Wf1, Wf2, bf2, Wf3, bf3, out);
}

// round 8
// speedup vs baseline: 1.2072x; 1.0220x over previous
#include <cuda_runtime.h>
#include <math.h>

#define NN 8192
#define NEI 8
#define NE (NN*NEI)
#define EPSV 1e-5f

// ---------------- scratch (static device memory; no runtime alloc) -------------
__device__ float4 g_posq[NN];    // (x, y, z, |p|^2) fp32 (query side)
__device__ float4 g_posq2[NN];   // (2x, 2y, 2z, |p|^2) fp32 (candidate side)
__device__ int    g_nbr[NE];
__device__ float  g_sh2[NE*5];
__device__ int    g_cnt[NN];
__device__ int    g_rowptr[NN+1];
__device__ int    g_cursor[NN];
__device__ int    g_csr[NE];
__device__ float  g_x0[NN*32];
__device__ float  g_x1[NN*48];
__device__ float  g_x2[NN*40];
__device__ float  g_y0[NN*32];
__device__ float  g_y1[NN*48];
__device__ float  g_y2[NN*40];
__device__ float  g_K[405];
__device__ float  g_scale0[32], g_shift0[32], g_scale1[16], g_scale2[8];

// K tensor layout offsets ([o][i][j] row-major per path)
// paths: (0,0,0)@0 sz1 | (0,2,2)@1 sz25 | (1,0,1)@26 sz9 | (1,2,1)@35 sz45 |
// (1,2,2)@80 sz75 | (2,0,2)@155 sz25 | (2,2,0)@180 sz25 | (2,2,1)@205 sz75 | (2,2,2)@280 sz125

// ---------------- K tensor init (fp32 — FP64 is ~1/64 rate on sm_103a) --------
__device__ float ffact(int n){ float r=1.f; for(int i=2;i<=n;i++) r*=(float)i; return r; }

__device__ float cg_coef_f(int j1,int m1,int j2,int m2,int j3,int m3){
  if(m1+m2!=m3 || j3<abs(j1-j2) || j3>j1+j2) return 0.f;
  float pre = sqrtf((2.f*j3+1.f)*ffact(j3+j1-j2)*ffact(j3-j1+j2)*ffact(j1+j2-j3)/ffact(j1+j2+j3+1));
  pre *= sqrtf(ffact(j3+m3)*ffact(j3-m3)*ffact(j1-m1)*ffact(j1+m1)*ffact(j2-m2)*ffact(j2+m2));
  float s=0.f;
  for(int k=0;k<=j1+j2-j3;k++){
    int d0=k, d1=j1+j2-j3-k, d2=j1-m1-k, d3=j2+m2-k, d4=j3-j2+m1+k, d5=j3-j1-m2+k;
    if(d0<0||d1<0||d2<0||d3<0||d4<0||d5<0) continue;
    float den = ffact(d0)*ffact(d1)*ffact(d2)*ffact(d3)*ffact(d4)*ffact(d5);
    s += ((k&1)? -1.f:1.f)/den;
  }
  return pre*s;
}

__device__ void q_entry_f(int l,int r,int c,float* re,float* im){
  int a=r-l, b=c-l; *re=0.f; *im=0.f;
  if(a==0 && b==0){ *re=1.f; return; }
  if(abs(a)!=abs(b) || a==0 || b==0) return;
  int m=abs(a); float s=0.70710678118654752f; float sgn=(m&1)? -1.f:1.f;
  if(a==m && b==m)       *re = sgn*s;
  else if(a==m && b==-m) *re = s;
  else if(a==-m && b==m) *im = -sgn*s;
  else                   *im = s;
}

__global__ void k_initK(){
  const int L1[9]={0,0,1,1,1,2,2,2,2};
  const int L2[9]={0,2,0,2,2,0,2,2,2};
  const int L3[9]={0,2,1,1,2,2,0,1,2};
  const int OFF[9]={0,1,26,35,80,155,180,205,280};
  int p=blockIdx.x, t=threadIdx.x;
  int l1=L1[p], l2=L2[p], l3=L3[p];
  int d1=2*l1+1, d2=2*l2+1, d3=2*l3+1;
  int tot=d1*d2*d3;
  __shared__ float s_re[125], s_im[125];
  __shared__ int s_useim;
  float re=0.f, im=0.f;
  if(t<tot){
    int c=t/(d1*d2); int rem=t-(c*d1*d2); int a=rem/d2; int b=rem-a*d2;
    for(int C=0;C<d3;C++){
      float q3r,q3i; q_entry_f(l3,c,C,&q3r,&q3i); q3i=-q3i;  // conj
      if(q3r==0.f && q3i==0.f) continue;
      for(int A=0;A<d1;A++){
        float q1r,q1i; q_entry_f(l1,a,A,&q1r,&q1i);
        if(q1r==0.f && q1i==0.f) continue;
        for(int B=0;B<d2;B++){
          float q2r,q2i; q_entry_f(l2,b,B,&q2r,&q2i);
          if(q2r==0.f && q2i==0.f) continue;
          float cgv = cg_coef_f(l1,A-l1,l2,B-l2,l3,C-l3);
          if(cgv==0.f) continue;
          float xr=q3r*q1r-q3i*q1i, xi=q3r*q1i+q3i*q1r;
          float yr=xr*q2r-xi*q2i,  yi=xr*q2i+xi*q2r;
          re += yr*cgv; im += yi*cgv;
        }
      }
    }
    s_re[t]=re; s_im[t]=im;
  }
  __syncthreads();
  if(t==0){
    float mr=0.f, mi=0.f;
    for(int k=0;k<tot;k++){ mr=fmaxf(mr,fabsf(s_re[k])); mi=fmaxf(mi,fabsf(s_im[k])); }
    s_useim = (mi>mr)?1:0;
  }
  __syncthreads();
  if(t<tot) g_K[OFF[p]+t] = s_useim ? s_im[t] : s_re[t];
}

// ---------------- prep -----------------------------------------------------
__global__ void k_prep(const float* __restrict__ pos){
  int n=blockIdx.x*blockDim.x+threadIdx.x;
  if(n>=NN) return;
  float x=pos[n*3+0], y=pos[n*3+1], z=pos[n*3+2];
  float sq = __fadd_rn(__fadd_rn(__fmul_rn(x,x),__fmul_rn(y,y)),__fmul_rn(z,z));
  float4 q;  q.x=x;      q.y=y;      q.z=z;      q.w=sq;  g_posq[n]=q;
  float4 q2; q2.x=2.f*x; q2.y=2.f*y; q2.z=2.f*z; q2.w=sq; g_posq2[n]=q2;
  g_cnt[n]=0;
}

__global__ void k_initx(const float* __restrict__ W_emb){
  int t=blockIdx.x*blockDim.x+threadIdx.x;
  if(t < NN*32)       g_x0[t] = W_emb[t & 31];
  else if(t < NN*80)  g_x1[t-NN*32] = 0.f;
  else if(t < NN*120) g_x2[t-NN*80] = 0.f;
}

// ---------------- KNN (d2 bit-pattern frozen: matches reference) ------------
// Candidate coords pre-scaled by 2 (exact): fmaf chain yields 2*dot bit-exactly,
// so d2 = rn(rn(qw+pw) - dot2) is identical to rn(rn(qw+pw) - rn(2*dot)).
__device__ __forceinline__ void topk_insert(float (&bv)[9], int (&bi)[9], float v, int j){
  float cv=v; int ci=j;
  #pragma unroll
  for(int k=0;k<9;k++){
    bool sw = (cv<bv[k]) || (cv==bv[k] && ci<bi[k]);
    float tv=bv[k]; int ti=bi[k];
    if(sw){ bv[k]=cv; bi[k]=ci; cv=tv; ci=ti; }
  }
}

__global__ void __launch_bounds__(128) k_knn(){
  int warp = threadIdx.x>>5, lane = threadIdx.x&31;
  int i = blockIdx.x*4 + warp;
  float4 q = g_posq[i];
  float bv[9]; int bi[9];
  #pragma unroll
  for(int k=0;k<9;k++){ bv[k]=INFINITY; bi[k]=0x7fffffff; }
  __shared__ float4 tile[256];
  for(int jt=0; jt<NN; jt+=256){
    __syncthreads();
    tile[threadIdx.x]     = g_posq2[jt+threadIdx.x];
    tile[threadIdx.x+128] = g_posq2[jt+threadIdx.x+128];
    __syncthreads();
    #pragma unroll
    for(int k=0;k<8;k++){
      int jj = lane + k*32;
      float4 p = tile[jj];
      float dot2 = __fmaf_rn(q.z, p.z, __fmaf_rn(q.y, p.y, __fmul_rn(q.x, p.x)));
      float d2   = __fsub_rn(__fadd_rn(q.w, p.w), dot2);
      if(d2 <= bv[8]) topk_insert(bv, bi, d2, jt+jj);
    }
  }
  // warp tree-merge of sorted 9-lists down to lane 0
  #pragma unroll
  for(int off=16; off>=1; off>>=1){
    float ov[9]; int oi[9];
    #pragma unroll
    for(int k=0;k<9;k++){
      ov[k]=__shfl_down_sync(0xffffffffu, bv[k], off);
      oi[k]=__shfl_down_sync(0xffffffffu, bi[k], off);
    }
    #pragma unroll
    for(int k=0;k<9;k++){
      if(ov[k] <= bv[8]) topk_insert(bv,bi,ov[k],oi[k]);
      else break;
    }
  }
  if(lane==0){
    #pragma unroll
    for(int r=0;r<8;r++) g_nbr[i*NEI+r] = bi[1+r];   // drop slot 0 (self), like idx[:,1:]
  }
}

// ---------------- edge geometry (sh2) + in-degree histogram -----------------
__global__ void k_edgegeo(const float* __restrict__ pos){
  int e=blockIdx.x*blockDim.x+threadIdx.x;
  if(e>=NE) return;
  int s=e>>3; int d=g_nbr[e];
  float ex=pos[d*3+0]-pos[s*3+0];
  float ey=pos[d*3+1]-pos[s*3+1];
  float ez=pos[d*3+2]-pos[s*3+2];
  float nrm = sqrtf(ex*ex+ey*ey+ez*ez) + 1e-12f;
  float x=ex/nrm, y=ey/nrm, z=ez/nrm;
  const float s15 = 3.8729833462074170f;  // sqrt(15)
  const float s5  = 2.2360679774997896f;  // sqrt(5)
  g_sh2[e*5+0] = s15*x*y;
  g_sh2[e*5+1] = s15*y*z;
  g_sh2[e*5+2] = 0.5f*s5*(3.f*z*z-1.f);
  g_sh2[e*5+3] = s15*x*z;
  g_sh2[e*5+4] = 0.5f*s15*(x*x-y*y);
  atomicAdd(&g_cnt[d],1);
}

// ---------------- exclusive scan (1 block) ----------------------------------
__global__ void k_scan(){
  __shared__ int tsum[1024];
  int t=threadIdx.x;
  int base=t*8; int local[8]; int s=0;
  #pragma unroll
  for(int k=0;k<8;k++){ local[k]=s; s+=g_cnt[base+k]; }
  tsum[t]=s; __syncthreads();
  for(int off=1; off<1024; off<<=1){
    int v = (t>=off)? tsum[t-off] : 0;
    __syncthreads();
    tsum[t]+=v;
    __syncthreads();
  }
  int prev = (t==0)?0:tsum[t-1];
  #pragma unroll
  for(int k=0;k<8;k++){ int val=prev+local[k]; g_rowptr[base+k]=val; g_cursor[base+k]=val; }
  if(t==1023) g_rowptr[NN]=tsum[1023];
}

__global__ void k_scatter(){
  int e=blockIdx.x*blockDim.x+threadIdx.x;
  if(e>=NE) return;
  int d=g_nbr[e];
  int p=atomicAdd(&g_cursor[d],1);
  g_csr[p]=e;
}

// sort each CSR row ascending -> fully deterministic aggregation order
__global__ void k_sortrows(){
  int n=blockIdx.x*blockDim.x+threadIdx.x;
  if(n>=NN) return;
  int b=g_rowptr[n], e2=g_rowptr[n+1];
  for(int i=b+1;i<e2;i++){
    int v=g_csr[i]; int j=i-1;
    while(j>=b && g_csr[j]>v){ g_csr[j+1]=g_csr[j]; j--; }
    g_csr[j+1]=v;
  }
}

// ---------------- factored S: S_oi = sum_j K[o][i][j]*sh[j] -----------------
// sS layout: p2S@0(5: o) | p4S@5(9: m*3+i) | p5S@14(15: o*3+i) | p7S@29(5: i)
//            | p8S@34(15: m*5+i) | p9S@49(25: o*5+i)   total 74
__device__ __forceinline__ float compute_S(int t, const float* sh, const float* sK){
  int off; 
  if(t<5)       off = 1   + t*5;                               // p2: o=t
  else if(t<14){ int x=t-5;  off = 35  + (x/3)*15 + (x%3)*5; } // p4
  else if(t<29){ int x=t-14; off = 80  + (x/3)*15 + (x%3)*5; } // p5
  else if(t<34) off = 180 + (t-29)*5;                           // p7: i
  else if(t<49){ int x=t-34; off = 205 + (x/5)*25 + (x%5)*5; } // p8
  else         { int x=t-49; off = 280 + (x/5)*25 + (x%5)*5; } // p9
  float r = sK[off]*sh[0];
  r = __fmaf_rn(sK[off+1], sh[1], r);
  r = __fmaf_rn(sK[off+2], sh[2], r);
  r = __fmaf_rn(sK[off+3], sh[3], r);
  r = __fmaf_rn(sK[off+4], sh[4], r);
  return r;
}

// ---------------- per-slot message value (factored) -------------------------
__device__ __forceinline__ float slot_val2(int s, const float* X, const float* S,
                                           const float* sK, const float* sw){
  const float* x0=X; const float* x1=X+32; const float* x2=X+80;
  if(s<40){
    if(s<32) return x0[s]*sK[0]*sw[s];                         // p1 (0,0,0)
    int u=s-32; float t=0.f;                                    // p7 (2,2,0)
    #pragma unroll
    for(int i=0;i<5;i++) t = __fmaf_rn(x2[u*5+i], S[29+i], t);
    return t*sw[120+u];
  } else if(s<160){
    int q=s-40; int u=q/3, m=q-3*u;
    if(u<16){                                                   // p3 (1,0,1)
      float t=0.f;
      #pragma unroll
      for(int i=0;i<3;i++) t = __fmaf_rn(x1[u*3+i], sK[26+m*3+i], t);
      return t*sw[64+u];
    }
    if(u<32){                                                   // p4 (1,2,1)
      int uu=u-16; float t=0.f;
      #pragma unroll
      for(int i=0;i<3;i++) t = __fmaf_rn(x1[uu*3+i], S[5+m*3+i], t);
      return t*sw[80+uu];
    }
    int uu=u-32; float t=0.f;                                   // p8 (2,2,1)
    #pragma unroll
    for(int i=0;i<5;i++) t = __fmaf_rn(x2[uu*5+i], S[34+m*5+i], t);
    return t*sw[128+uu];
  } else {
    int q=s-160; int u=q/5, o=q-5*u;
    if(u<32) return x0[u]*S[o]*sw[32+u];                        // p2 (0,2,2)
    if(u<48){                                                   // p5 (1,2,2)
      int uu=u-32; float t=0.f;
      #pragma unroll
      for(int i=0;i<3;i++) t = __fmaf_rn(x1[uu*3+i], S[14+o*3+i], t);
      return t*sw[96+uu];
    }
    if(u<56){                                                   // p6 (2,0,2)
      int uu=u-48; float t=0.f;
      #pragma unroll
      for(int i=0;i<5;i++) t = __fmaf_rn(x2[uu*5+i], sK[155+o*5+i], t);
      return t*sw[112+uu];
    }
    int uu=u-56; float t=0.f;                                   // p9 (2,2,2)
    #pragma unroll
    for(int i=0;i<5;i++) t = __fmaf_rn(x2[uu*5+i], S[49+o*5+i], t);
    return t*sw[136+uu];
  }
}

__device__ __forceinline__ float load_edge_val(int t, int e){
  int s=e>>3;
  if(t<32)  return g_x0[s*32+t];
  if(t<80)  return g_x1[s*48+(t-32)];
  if(t<120) return g_x2[s*40+(t-80)];
  if(t<125) return g_sh2[e*5+(t-120)];
  return 0.f;
}

// ---------------- aggregate + linear (block per dst node) -------------------
__global__ void k_aggregate(int l, const float* __restrict__ tp_w,
                            const float* __restrict__ W0g,
                            const float* __restrict__ W1g,
                            const float* __restrict__ W2g){
  int d=blockIdx.x; int t=threadIdx.x;
  __shared__ float sK[405];
  __shared__ float sw[144];
  __shared__ float xs[2][128];
  __shared__ float sS[2][80];
  __shared__ float sa[480];
  for(int i=t;i<405;i+=128) sK[i]=g_K[i];
  for(int i=t;i<144;i+=128) sw[i]=tp_w[l*144+i];
  float acc0=0.f, acc1=0.f, acc2=0.f, acc3=0.f;
  int b=g_rowptr[d], deg=g_rowptr[d+1]-b;
  float v = 0.f;
  if(deg>0) v = load_edge_val(t, g_csr[b]);
  __syncthreads();   // sK/sw ready
  for(int q=0;q<deg;q++){
    int buf=q&1;
    if(t<125) xs[buf][t]=v;
    __syncthreads();                                    // xs[buf] ready
    if(q+1<deg) v = load_edge_val(t, g_csr[b+q+1]);     // prefetch (overlaps)
    if(t<74) sS[buf][t] = compute_S(t, &xs[buf][120], sK);
    __syncthreads();                                    // sS[buf] ready
    const float* X=xs[buf]; const float* S=sS[buf];
    acc0 += slot_val2(t,     X, S, sK, sw);
    acc1 += slot_val2(t+128, X, S, sK, sw);
    acc2 += slot_val2(t+256, X, S, sK, sw);
    if(t<96) acc3 += slot_val2(t+384, X, S, sK, sw);
  }
  __syncthreads();
  sa[t]=acc0; sa[t+128]=acc1; sa[t+256]=acc2; if(t<96) sa[t+384]=acc3;
  __syncthreads();
  const float* W0=W0g+l*1280; const float* W1=W1g+l*640; const float* W2=W2g+l*512;
  const float inv40 = 0.15811388300841897f;  // 1/sqrt(40)
  if(t<32){
    float s=0.f;
    #pragma unroll
    for(int u=0;u<40;u++) s += sa[u]*__ldg(&W0[u*32+t]);
    g_y0[d*32+t] = s*inv40;
  } else if(t<80){
    int q2=t-32; int v2=q2/3, m=q2-3*v2; float s=0.f;
    #pragma unroll
    for(int u=0;u<40;u++) s += sa[40+u*3+m]*__ldg(&W1[u*16+v2]);
    g_y1[d*48+v2*3+m] = s*inv40;
  } else if(t<120){
    int q2=t-80; int v2=q2/5, o=q2-5*v2; float s=0.f;
    #pragma unroll
    for(int u=0;u<64;u++) s += sa[160+u*5+o]*__ldg(&W2[u*8+v2]);
    g_y2[d*40+v2*5+o] = s*0.125f;       // 1/sqrt(64)
  }
}

// ---------------- BN stats (deterministic, double accum) --------------------
__global__ void k_stats(int l, const float* __restrict__ bw0, const float* __restrict__ bb0,
                        const float* __restrict__ bw1, const float* __restrict__ bw2){
  int b=blockIdx.x, t=threadIdx.x;
  __shared__ double r1[256], r2[256];
  double s1=0.0, s2=0.0;
  if(b<32){
    int c=b;
    for(int n=t;n<NN;n+=256){ double v=g_y0[n*32+c]; s1+=v; s2+=v*v; }
  } else if(b<48){
    int c=b-32;
    for(int n=t;n<NN;n+=256){
      #pragma unroll
      for(int m=0;m<3;m++){ double v=g_y1[n*48+c*3+m]; s2+=v*v; }
    }
  } else {
    int c=b-48;
    for(int n=t;n<NN;n+=256){
      #pragma unroll
      for(int o=0;o<5;o++){ double v=g_y2[n*40+c*5+o]; s2+=v*v; }
    }
  }
  r1[t]=s1; r2[t]=s2; __syncthreads();
  for(int off=128; off>=1; off>>=1){
    if(t<off){ r1[t]+=r1[t+off]; r2[t]+=r2[t+off]; }
    __syncthreads();
  }
  if(t==0){
    if(b<32){
      int c=b;
      double mu=r1[0]/(double)NN;
      double var=r2[0]/(double)NN - mu*mu;
      float scale = bw0[l*32+c]/sqrtf((float)var + EPSV);
      g_scale0[c]=scale;
      g_shift0[c]=bb0[l*32+c]-(float)mu*scale;
    } else if(b<48){
      int c=b-32;
      float mean=(float)(r2[0]/(double)(NN*3));
      g_scale1[c]=bw1[l*16+c]/sqrtf(mean+EPSV);
    } else {
      int c=b-48;
      float mean=(float)(r2[0]/(double)(NN*5));
      g_scale2[c]=bw2[l*8+c]/sqrtf(mean+EPSV);
    }
  }
}

// ---------------- normalize + relu + residual -------------------------------
__global__ void k_update(){
  int t=blockIdx.x*blockDim.x+threadIdx.x;
  if(t>=NN*120) return;
  int n=t/120, r=t-n*120;
  if(r<32){
    int idx=n*32+r;
    float v=g_y0[idx]*g_scale0[r]+g_shift0[r];
    g_x0[idx]+=fmaxf(v,0.f);
  } else if(r<80){
    int q=r-32; int u=q/3; int idx=n*48+q;
    float v=g_y1[idx]*g_scale1[u];
    g_x1[idx]+=fmaxf(v,0.f);
  } else {
    int q=r-80; int u=q/5; int idx=n*40+q;
    float v=g_y2[idx]*g_scale2[u];
    g_x2[idx]+=fmaxf(v,0.f);
  }
}

// ---------------- head MLP ---------------------------------------------------
__global__ void k_head(const float* __restrict__ Wf1, const float* __restrict__ Wf2,
                       const float* __restrict__ bf2, const float* __restrict__ Wf3,
                       const float* __restrict__ bf3, float* __restrict__ out){
  __shared__ float sW1[1024], sW2[512], sb2[16], sW3[32], sb3[2];
  int t=threadIdx.x;
  for(int i=t;i<1024;i+=128) sW1[i]=Wf1[i];
  for(int i=t;i<512;i+=128)  sW2[i]=Wf2[i];
  if(t<16) sb2[t]=bf2[t];
  if(t<32) sW3[t]=Wf3[t];
  if(t<2)  sb3[t]=bf3[t];
  __syncthreads();
  int n=blockIdx.x*128+t;
  float xin[32];
  #pragma unroll
  for(int i=0;i<32;i++) xin[i]=g_x0[n*32+i];
  const float c1=0.1767766952966369f;  // 1/sqrt(32)
  float h1[32];
  #pragma unroll
  for(int j=0;j<32;j++){
    float s=0.f;
    #pragma unroll
    for(int i=0;i<32;i++) s += xin[i]*sW1[i*32+j];
    h1[j]=fmaxf(s*c1,0.f);
  }
  float h2[16];
  #pragma unroll
  for(int k=0;k<16;k++){
    float s=sb2[k];
    #pragma unroll
    for(int j=0;j<32;j++) s += h1[j]*sW2[j*16+k];
    h2[k]=fmaxf(s,0.f);
  }
  #pragma unroll
  for(int m=0;m<2;m++){
    float s=sb3[m];
    #pragma unroll
    for(int k=0;k<16;k++) s += h2[k]*sW3[k*2+m];
    out[n*2+m]=s;
  }
}

// ---------------- launch ------------------------------------------------------
extern "C" void kernel_launch(void* const* d_in, const int* in_sizes, int n_in,
                              void* d_out, int out_size){
  const float* pos    = (const float*)d_in[0];
  const float* W_emb  = (const float*)d_in[1];
  const float* tp_w   = (const float*)d_in[2];
  const float* lin_W0 = (const float*)d_in[3];
  const float* lin_W1 = (const float*)d_in[4];
  const float* lin_W2 = (const float*)d_in[5];
  const float* bn_w0  = (const float*)d_in[6];
  const float* bn_b0  = (const float*)d_in[7];
  const float* bn_w1  = (const float*)d_in[8];
  const float* bn_w2  = (const float*)d_in[9];
  const float* Wf1    = (const float*)d_in[10];
  const float* Wf2    = (const float*)d_in[11];
  const float* bf2    = (const float*)d_in[12];
  const float* Wf3    = (const float*)d_in[13];
  const float* bf3    = (const float*)d_in[14];
  float* out = (float*)d_out;

  k_initK<<<9,128>>>();
  k_prep<<<NN/256,256>>>(pos);
  k_initx<<<(NN*120+255)/256,256>>>(W_emb);
  k_knn<<<NN/4,128>>>();
  k_edgegeo<<<NE/256,256>>>(pos);
  k_scan<<<1,1024>>>();
  k_scatter<<<NE/256,256>>>();
  k_sortrows<<<NN/256,256>>>();
  for(int l=0;l<3;l++){
    k_aggregate<<<NN,128>>>(l, tp_w, lin_W0, lin_W1, lin_W2);
    k_stats<<<56,256>>>(l, bn_w0, bn_b0, bn_w1, bn_w2);
    k_update<<<(NN*120+255)/256,256>>>();
  }
  k_head<<<NN/128,128>>>(Wf1, Wf2, bf2, Wf3, bf3, out);
}

// round 9
// speedup vs baseline: 1.8328x; 1.5182x over previous
#include <cuda_runtime.h>
#include <math.h>

#define NN 8192
#define NEI 8
#define NE (NN*NEI)
#define EPSV 1e-5f

// ---------------- scratch (static device memory; no runtime alloc) -------------
__device__ float4 g_posq[NN];    // (x, y, z, |p|^2) fp32 (query side)
__device__ float4 g_posq2[NN];   // (2x, 2y, 2z, |p|^2) fp32 (candidate side)
__device__ int    g_nbr[NE];
__device__ float  g_sh2[NE*5];
__device__ int    g_cnt[NN];
__device__ int    g_rowptr[NN+1];
__device__ int    g_cursor[NN];
__device__ int    g_csr[NE];
__device__ float  g_x0[NN*32];
__device__ float  g_x1[NN*48];
__device__ float  g_x2[NN*40];
__device__ float  g_y0[NN*32];
__device__ float  g_y1[NN*48];
__device__ float  g_y2[NN*40];
__device__ float  g_K[405];
__device__ float  g_scale0[32], g_shift0[32], g_scale1[16], g_scale2[8];

// K tensor layout offsets ([o][i][j] row-major per path)
// paths: (0,0,0)@0 sz1 | (0,2,2)@1 sz25 | (1,0,1)@26 sz9 | (1,2,1)@35 sz45 |
// (1,2,2)@80 sz75 | (2,0,2)@155 sz25 | (2,2,0)@180 sz25 | (2,2,1)@205 sz75 | (2,2,2)@280 sz125

// ---------------- K tensor init (fp32) -----------------------------------------
__device__ float ffact(int n){ float r=1.f; for(int i=2;i<=n;i++) r*=(float)i; return r; }

__device__ float cg_coef_f(int j1,int m1,int j2,int m2,int j3,int m3){
  if(m1+m2!=m3 || j3<abs(j1-j2) || j3>j1+j2) return 0.f;
  float pre = sqrtf((2.f*j3+1.f)*ffact(j3+j1-j2)*ffact(j3-j1+j2)*ffact(j1+j2-j3)/ffact(j1+j2+j3+1));
  pre *= sqrtf(ffact(j3+m3)*ffact(j3-m3)*ffact(j1-m1)*ffact(j1+m1)*ffact(j2-m2)*ffact(j2+m2));
  float s=0.f;
  for(int k=0;k<=j1+j2-j3;k++){
    int d0=k, d1=j1+j2-j3-k, d2=j1-m1-k, d3=j2+m2-k, d4=j3-j2+m1+k, d5=j3-j1-m2+k;
    if(d0<0||d1<0||d2<0||d3<0||d4<0||d5<0) continue;
    float den = ffact(d0)*ffact(d1)*ffact(d2)*ffact(d3)*ffact(d4)*ffact(d5);
    s += ((k&1)? -1.f:1.f)/den;
  }
  return pre*s;
}

__device__ void q_entry_f(int l,int r,int c,float* re,float* im){
  int a=r-l, b=c-l; *re=0.f; *im=0.f;
  if(a==0 && b==0){ *re=1.f; return; }
  if(abs(a)!=abs(b) || a==0 || b==0) return;
  int m=abs(a); float s=0.70710678118654752f; float sgn=(m&1)? -1.f:1.f;
  if(a==m && b==m)       *re = sgn*s;
  else if(a==m && b==-m) *re = s;
  else if(a==-m && b==m) *im = -sgn*s;
  else                   *im = s;
}

__global__ void k_initK(){
  const int L1[9]={0,0,1,1,1,2,2,2,2};
  const int L2[9]={0,2,0,2,2,0,2,2,2};
  const int L3[9]={0,2,1,1,2,2,0,1,2};
  const int OFF[9]={0,1,26,35,80,155,180,205,280};
  int p=blockIdx.x, t=threadIdx.x;
  int l1=L1[p], l2=L2[p], l3=L3[p];
  int d1=2*l1+1, d2=2*l2+1, d3=2*l3+1;
  int tot=d1*d2*d3;
  __shared__ float s_re[125], s_im[125];
  __shared__ int s_useim;
  float re=0.f, im=0.f;
  if(t<tot){
    int c=t/(d1*d2); int rem=t-(c*d1*d2); int a=rem/d2; int b=rem-a*d2;
    for(int C=0;C<d3;C++){
      float q3r,q3i; q_entry_f(l3,c,C,&q3r,&q3i); q3i=-q3i;  // conj
      if(q3r==0.f && q3i==0.f) continue;
      for(int A=0;A<d1;A++){
        float q1r,q1i; q_entry_f(l1,a,A,&q1r,&q1i);
        if(q1r==0.f && q1i==0.f) continue;
        for(int B=0;B<d2;B++){
          float q2r,q2i; q_entry_f(l2,b,B,&q2r,&q2i);
          if(q2r==0.f && q2i==0.f) continue;
          float cgv = cg_coef_f(l1,A-l1,l2,B-l2,l3,C-l3);
          if(cgv==0.f) continue;
          float xr=q3r*q1r-q3i*q1i, xi=q3r*q1i+q3i*q1r;
          float yr=xr*q2r-xi*q2i,  yi=xr*q2i+xi*q2r;
          re += yr*cgv; im += yi*cgv;
        }
      }
    }
    s_re[t]=re; s_im[t]=im;
  }
  __syncthreads();
  if(t==0){
    float mr=0.f, mi=0.f;
    for(int k=0;k<tot;k++){ mr=fmaxf(mr,fabsf(s_re[k])); mi=fmaxf(mi,fabsf(s_im[k])); }
    s_useim = (mi>mr)?1:0;
  }
  __syncthreads();
  if(t<tot) g_K[OFF[p]+t] = s_useim ? s_im[t] : s_re[t];
}

// ---------------- prep -----------------------------------------------------
__global__ void k_prep(const float* __restrict__ pos){
  int n=blockIdx.x*blockDim.x+threadIdx.x;
  if(n>=NN) return;
  float x=pos[n*3+0], y=pos[n*3+1], z=pos[n*3+2];
  float sq = __fadd_rn(__fadd_rn(__fmul_rn(x,x),__fmul_rn(y,y)),__fmul_rn(z,z));
  float4 q;  q.x=x;      q.y=y;      q.z=z;      q.w=sq;  g_posq[n]=q;
  float4 q2; q2.x=2.f*x; q2.y=2.f*y; q2.z=2.f*z; q2.w=sq; g_posq2[n]=q2;
  g_cnt[n]=0;
}

__global__ void k_initx(const float* __restrict__ W_emb){
  int t=blockIdx.x*blockDim.x+threadIdx.x;
  if(t < NN*32)       g_x0[t] = W_emb[t & 31];
  else if(t < NN*80)  g_x1[t-NN*32] = 0.f;
  else if(t < NN*120) g_x2[t-NN*80] = 0.f;
}

// ---------------- KNN: warp-cooperative replicated top-9 ---------------------
// d2 bit-pattern frozen (matches reference). Candidate coords pre-scaled by 2
// (exact), so the fmaf chain produces 2*dot bit-exactly.
__device__ __forceinline__ void topk_insert(float (&bv)[9], int (&bi)[9], float v, int j){
  float cv=v; int ci=j;
  #pragma unroll
  for(int k=0;k<9;k++){
    bool sw = (cv<bv[k]) || (cv==bv[k] && ci<bi[k]);
    float tv=bv[k]; int ti=bi[k];
    if(sw){ bv[k]=cv; bi[k]=ci; cv=tv; ci=ti; }
  }
}

__global__ void __launch_bounds__(256) k_knn(){
  int warp = threadIdx.x>>5, lane = threadIdx.x&31;
  int i = blockIdx.x*8 + warp;
  float4 q = g_posq[i];
  // replicated warp-global top-9 (identical in every lane; all ops uniform)
  float bv[9]; int bi[9];
  #pragma unroll
  for(int k=0;k<9;k++){ bv[k]=INFINITY; bi[k]=0x7fffffff; }
  __shared__ float4 tile[256];
  for(int jt=0; jt<NN; jt+=256){
    __syncthreads();
    tile[threadIdx.x] = g_posq2[jt+threadIdx.x];
    __syncthreads();
    #pragma unroll
    for(int k=0;k<8;k++){
      int jj = lane + k*32;
      float4 p = tile[jj];
      float dot2 = __fmaf_rn(q.z, p.z, __fmaf_rn(q.y, p.y, __fmul_rn(q.x, p.x)));
      float d2   = __fsub_rn(__fadd_rn(q.w, p.w), dot2);
      unsigned mask = __ballot_sync(0xffffffffu, d2 <= bv[8]);
      while(mask){                      // uniform across warp (mask identical)
        int b = __ffs(mask)-1; mask &= mask-1;
        float v = __shfl_sync(0xffffffffu, d2, b);
        int  id = jt + b + k*32;
        if(v < bv[8] || (v==bv[8] && id < bi[8]))
          topk_insert(bv, bi, v, id);   // all lanes insert identically
      }
    }
  }
  if(lane==0){
    #pragma unroll
    for(int r=0;r<8;r++) g_nbr[i*NEI+r] = bi[1+r];   // drop slot 0 (self), like idx[:,1:]
  }
}

// ---------------- edge geometry (sh2) + in-degree histogram -----------------
__global__ void k_edgegeo(const float* __restrict__ pos){
  int e=blockIdx.x*blockDim.x+threadIdx.x;
  if(e>=NE) return;
  int s=e>>3; int d=g_nbr[e];
  float ex=pos[d*3+0]-pos[s*3+0];
  float ey=pos[d*3+1]-pos[s*3+1];
  float ez=pos[d*3+2]-pos[s*3+2];
  float nrm = sqrtf(ex*ex+ey*ey+ez*ez) + 1e-12f;
  float x=ex/nrm, y=ey/nrm, z=ez/nrm;
  const float s15 = 3.8729833462074170f;  // sqrt(15)
  const float s5  = 2.2360679774997896f;  // sqrt(5)
  g_sh2[e*5+0] = s15*x*y;
  g_sh2[e*5+1] = s15*y*z;
  g_sh2[e*5+2] = 0.5f*s5*(3.f*z*z-1.f);
  g_sh2[e*5+3] = s15*x*z;
  g_sh2[e*5+4] = 0.5f*s15*(x*x-y*y);
  atomicAdd(&g_cnt[d],1);
}

// ---------------- exclusive scan (1 block) ----------------------------------
__global__ void k_scan(){
  __shared__ int tsum[1024];
  int t=threadIdx.x;
  int base=t*8; int local[8]; int s=0;
  #pragma unroll
  for(int k=0;k<8;k++){ local[k]=s; s+=g_cnt[base+k]; }
  tsum[t]=s; __syncthreads();
  for(int off=1; off<1024; off<<=1){
    int v = (t>=off)? tsum[t-off] : 0;
    __syncthreads();
    tsum[t]+=v;
    __syncthreads();
  }
  int prev = (t==0)?0:tsum[t-1];
  #pragma unroll
  for(int k=0;k<8;k++){ int val=prev+local[k]; g_rowptr[base+k]=val; g_cursor[base+k]=val; }
  if(t==1023) g_rowptr[NN]=tsum[1023];
}

__global__ void k_scatter(){
  int e=blockIdx.x*blockDim.x+threadIdx.x;
  if(e>=NE) return;
  int d=g_nbr[e];
  int p=atomicAdd(&g_cursor[d],1);
  g_csr[p]=e;
}

// sort each CSR row ascending -> fully deterministic aggregation order
__global__ void k_sortrows(){
  int n=blockIdx.x*blockDim.x+threadIdx.x;
  if(n>=NN) return;
  int b=g_rowptr[n], e2=g_rowptr[n+1];
  for(int i=b+1;i<e2;i++){
    int v=g_csr[i]; int j=i-1;
    while(j>=b && g_csr[j]>v){ g_csr[j+1]=g_csr[j]; j--; }
    g_csr[j+1]=v;
  }
}

// ---------------- factored S: S_oi = sum_j K[o][i][j]*sh[j] -----------------
// sS layout: p2S@0(5: o) | p4S@5(9: m*3+i) | p5S@14(15: o*3+i) | p7S@29(5: i)
//            | p8S@34(15: m*5+i) | p9S@49(25: o*5+i)   total 74
__device__ __forceinline__ float compute_S(int t, const float* sh, const float* sK){
  int off; 
  if(t<5)       off = 1   + t*5;                               // p2: o=t
  else if(t<14){ int x=t-5;  off = 35  + (x/3)*15 + (x%3)*5; } // p4
  else if(t<29){ int x=t-14; off = 80  + (x/3)*15 + (x%3)*5; } // p5
  else if(t<34) off = 180 + (t-29)*5;                           // p7: i
  else if(t<49){ int x=t-34; off = 205 + (x/5)*25 + (x%5)*5; } // p8
  else         { int x=t-49; off = 280 + (x/5)*25 + (x%5)*5; } // p9
  float r = sK[off]*sh[0];
  r = __fmaf_rn(sK[off+1], sh[1], r);
  r = __fmaf_rn(sK[off+2], sh[2], r);
  r = __fmaf_rn(sK[off+3], sh[3], r);
  r = __fmaf_rn(sK[off+4], sh[4], r);
  return r;
}

// ---------------- per-slot message value (factored) -------------------------
__device__ __forceinline__ float slot_val2(int s, const float* X, const float* S,
                                           const float* sK, const float* sw){
  const float* x0=X; const float* x1=X+32; const float* x2=X+80;
  if(s<40){
    if(s<32) return x0[s]*sK[0]*sw[s];                         // p1 (0,0,0)
    int u=s-32; float t=0.f;                                    // p7 (2,2,0)
    #pragma unroll
    for(int i=0;i<5;i++) t = __fmaf_rn(x2[u*5+i], S[29+i], t);
    return t*sw[120+u];
  } else if(s<160){
    int q=s-40; int u=q/3, m=q-3*u;
    if(u<16){                                                   // p3 (1,0,1)
      float t=0.f;
      #pragma unroll
      for(int i=0;i<3;i++) t = __fmaf_rn(x1[u*3+i], sK[26+m*3+i], t);
      return t*sw[64+u];
    }
    if(u<32){                                                   // p4 (1,2,1)
      int uu=u-16; float t=0.f;
      #pragma unroll
      for(int i=0;i<3;i++) t = __fmaf_rn(x1[uu*3+i], S[5+m*3+i], t);
      return t*sw[80+uu];
    }
    int uu=u-32; float t=0.f;                                   // p8 (2,2,1)
    #pragma unroll
    for(int i=0;i<5;i++) t = __fmaf_rn(x2[uu*5+i], S[34+m*5+i], t);
    return t*sw[128+uu];
  } else {
    int q=s-160; int u=q/5, o=q-5*u;
    if(u<32) return x0[u]*S[o]*sw[32+u];                        // p2 (0,2,2)
    if(u<48){                                                   // p5 (1,2,2)
      int uu=u-32; float t=0.f;
      #pragma unroll
      for(int i=0;i<3;i++) t = __fmaf_rn(x1[uu*3+i], S[14+o*3+i], t);
      return t*sw[96+uu];
    }
    if(u<56){                                                   // p6 (2,0,2)
      int uu=u-48; float t=0.f;
      #pragma unroll
      for(int i=0;i<5;i++) t = __fmaf_rn(x2[uu*5+i], sK[155+o*5+i], t);
      return t*sw[112+uu];
    }
    int uu=u-56; float t=0.f;                                   // p9 (2,2,2)
    #pragma unroll
    for(int i=0;i<5;i++) t = __fmaf_rn(x2[uu*5+i], S[49+o*5+i], t);
    return t*sw[136+uu];
  }
}

__device__ __forceinline__ float load_edge_val(int t, int e){
  int s=e>>3;
  if(t<32)  return g_x0[s*32+t];
  if(t<80)  return g_x1[s*48+(t-32)];
  if(t<120) return g_x2[s*40+(t-80)];
  if(t<125) return g_sh2[e*5+(t-120)];
  return 0.f;
}

// ---------------- aggregate + linear (block per dst node) -------------------
__global__ void k_aggregate(int l, const float* __restrict__ tp_w,
                            const float* __restrict__ W0g,
                            const float* __restrict__ W1g,
                            const float* __restrict__ W2g){
  int d=blockIdx.x; int t=threadIdx.x;
  __shared__ float sK[405];
  __shared__ float sw[144];
  __shared__ float xs[2][128];
  __shared__ float sS[2][80];
  __shared__ float sa[480];
  for(int i=t;i<405;i+=128) sK[i]=g_K[i];
  for(int i=t;i<144;i+=128) sw[i]=tp_w[l*144+i];
  float acc0=0.f, acc1=0.f, acc2=0.f, acc3=0.f;
  int b=g_rowptr[d], deg=g_rowptr[d+1]-b;
  float v = 0.f;
  if(deg>0) v = load_edge_val(t, g_csr[b]);
  __syncthreads();   // sK/sw ready
  for(int q=0;q<deg;q++){
    int buf=q&1;
    if(t<125) xs[buf][t]=v;
    __syncthreads();                                    // xs[buf] ready
    if(q+1<deg) v = load_edge_val(t, g_csr[b+q+1]);     // prefetch (overlaps)
    if(t<74) sS[buf][t] = compute_S(t, &xs[buf][120], sK);
    __syncthreads();                                    // sS[buf] ready
    const float* X=xs[buf]; const float* S=sS[buf];
    acc0 += slot_val2(t,     X, S, sK, sw);
    acc1 += slot_val2(t+128, X, S, sK, sw);
    acc2 += slot_val2(t+256, X, S, sK, sw);
    if(t<96) acc3 += slot_val2(t+384, X, S, sK, sw);
  }
  __syncthreads();
  sa[t]=acc0; sa[t+128]=acc1; sa[t+256]=acc2; if(t<96) sa[t+384]=acc3;
  __syncthreads();
  const float* W0=W0g+l*1280; const float* W1=W1g+l*640; const float* W2=W2g+l*512;
  const float inv40 = 0.15811388300841897f;  // 1/sqrt(40)
  if(t<32){
    float s=0.f;
    #pragma unroll
    for(int u=0;u<40;u++) s += sa[u]*__ldg(&W0[u*32+t]);
    g_y0[d*32+t] = s*inv40;
  } else if(t<80){
    int q2=t-32; int v2=q2/3, m=q2-3*v2; float s=0.f;
    #pragma unroll
    for(int u=0;u<40;u++) s += sa[40+u*3+m]*__ldg(&W1[u*16+v2]);
    g_y1[d*48+v2*3+m] = s*inv40;
  } else if(t<120){
    int q2=t-80; int v2=q2/5, o=q2-5*v2; float s=0.f;
    #pragma unroll
    for(int u=0;u<64;u++) s += sa[160+u*5+o]*__ldg(&W2[u*8+v2]);
    g_y2[d*40+v2*5+o] = s*0.125f;       // 1/sqrt(64)
  }
}

// ---------------- BN stats (deterministic, double accum) --------------------
__global__ void k_stats(int l, const float* __restrict__ bw0, const float* __restrict__ bb0,
                        const float* __restrict__ bw1, const float* __restrict__ bw2){
  int b=blockIdx.x, t=threadIdx.x;
  __shared__ double r1[256], r2[256];
  double s1=0.0, s2=0.0;
  if(b<32){
    int c=b;
    for(int n=t;n<NN;n+=256){ double v=g_y0[n*32+c]; s1+=v; s2+=v*v; }
  } else if(b<48){
    int c=b-32;
    for(int n=t;n<NN;n+=256){
      #pragma unroll
      for(int m=0;m<3;m++){ double v=g_y1[n*48+c*3+m]; s2+=v*v; }
    }
  } else {
    int c=b-48;
    for(int n=t;n<NN;n+=256){
      #pragma unroll
      for(int o=0;o<5;o++){ double v=g_y2[n*40+c*5+o]; s2+=v*v; }
    }
  }
  r1[t]=s1; r2[t]=s2; __syncthreads();
  for(int off=128; off>=1; off>>=1){
    if(t<off){ r1[t]+=r1[t+off]; r2[t]+=r2[t+off]; }
    __syncthreads();
  }
  if(t==0){
    if(b<32){
      int c=b;
      double mu=r1[0]/(double)NN;
      double var=r2[0]/(double)NN - mu*mu;
      float scale = bw0[l*32+c]/sqrtf((float)var + EPSV);
      g_scale0[c]=scale;
      g_shift0[c]=bb0[l*32+c]-(float)mu*scale;
    } else if(b<48){
      int c=b-32;
      float mean=(float)(r2[0]/(double)(NN*3));
      g_scale1[c]=bw1[l*16+c]/sqrtf(mean+EPSV);
    } else {
      int c=b-48;
      float mean=(float)(r2[0]/(double)(NN*5));
      g_scale2[c]=bw2[l*8+c]/sqrtf(mean+EPSV);
    }
  }
}

// ---------------- normalize + relu + residual -------------------------------
__global__ void k_update(){
  int t=blockIdx.x*blockDim.x+threadIdx.x;
  if(t>=NN*120) return;
  int n=t/120, r=t-n*120;
  if(r<32){
    int idx=n*32+r;
    float v=g_y0[idx]*g_scale0[r]+g_shift0[r];
    g_x0[idx]+=fmaxf(v,0.f);
  } else if(r<80){
    int q=r-32; int u=q/3; int idx=n*48+q;
    float v=g_y1[idx]*g_scale1[u];
    g_x1[idx]+=fmaxf(v,0.f);
  } else {
    int q=r-80; int u=q/5; int idx=n*40+q;
    float v=g_y2[idx]*g_scale2[u];
    g_x2[idx]+=fmaxf(v,0.f);
  }
}

// ---------------- head MLP ---------------------------------------------------
__global__ void k_head(const float* __restrict__ Wf1, const float* __restrict__ Wf2,
                       const float* __restrict__ bf2, const float* __restrict__ Wf3,
                       const float* __restrict__ bf3, float* __restrict__ out){
  __shared__ float sW1[1024], sW2[512], sb2[16], sW3[32], sb3[2];
  int t=threadIdx.x;
  for(int i=t;i<1024;i+=128) sW1[i]=Wf1[i];
  for(int i=t;i<512;i+=128)  sW2[i]=Wf2[i];
  if(t<16) sb2[t]=bf2[t];
  if(t<32) sW3[t]=Wf3[t];
  if(t<2)  sb3[t]=bf3[t];
  __syncthreads();
  int n=blockIdx.x*128+t;
  float xin[32];
  #pragma unroll
  for(int i=0;i<32;i++) xin[i]=g_x0[n*32+i];
  const float c1=0.1767766952966369f;  // 1/sqrt(32)
  float h1[32];
  #pragma unroll
  for(int j=0;j<32;j++){
    float s=0.f;
    #pragma unroll
    for(int i=0;i<32;i++) s += xin[i]*sW1[i*32+j];
    h1[j]=fmaxf(s*c1,0.f);
  }
  float h2[16];
  #pragma unroll
  for(int k=0;k<16;k++){
    float s=sb2[k];
    #pragma unroll
    for(int j=0;j<32;j++) s += h1[j]*sW2[j*16+k];
    h2[k]=fmaxf(s,0.f);
  }
  #pragma unroll
  for(int m=0;m<2;m++){
    float s=sb3[m];
    #pragma unroll
    for(int k=0;k<16;k++) s += h2[k]*sW3[k*2+m];
    out[n*2+m]=s;
  }
}

// ---------------- launch ------------------------------------------------------
extern "C" void kernel_launch(void* const* d_in, const int* in_sizes, int n_in,
                              void* d_out, int out_size){
  const float* pos    = (const float*)d_in[0];
  const float* W_emb  = (const float*)d_in[1];
  const float* tp_w   = (const float*)d_in[2];
  const float* lin_W0 = (const float*)d_in[3];
  const float* lin_W1 = (const float*)d_in[4];
  const float* lin_W2 = (const float*)d_in[5];
  const float* bn_w0  = (const float*)d_in[6];
  const float* bn_b0  = (const float*)d_in[7];
  const float* bn_w1  = (const float*)d_in[8];
  const float* bn_w2  = (const float*)d_in[9];
  const float* Wf1    = (const float*)d_in[10];
  const float* Wf2    = (const float*)d_in[11];
  const float* bf2    = (const float*)d_in[12];
  const float* Wf3    = (const float*)d_in[13];
  const float* bf3    = (const float*)d_in[14];
  float* out = (float*)d_out;

  k_initK<<<9,128>>>();
  k_prep<<<NN/256,256>>>(pos);
  k_initx<<<(NN*120+255)/256,256>>>(W_emb);
  k_knn<<<NN/8,256>>>();
  k_edgegeo<<<NE/256,256>>>(pos);
  k_scan<<<1,1024>>>();
  k_scatter<<<NE/256,256>>>();
  k_sortrows<<<NN/256,256>>>();
  for(int l=0;l<3;l++){
    k_aggregate<<<NN,128>>>(l, tp_w, lin_W0, lin_W1, lin_W2);
    k_stats<<<56,256>>>(l, bn_w0, bn_b0, bn_w1, bn_w2);
    k_update<<<(NN*120+255)/256,256>>>();
  }
  k_head<<<NN/128,128>>>(Wf1, Wf2, bf2, Wf3, bf3, out);
}